// round 16
// baseline (speedup 1.0000x reference)
#include <cuda_runtime.h>
#include <cuda_bf16.h>
#include <cstdint>

// RBF: out[i][j] = exp(-||x_i - y_j||^2), N=M=8192, D=64, fp32.
// dist2 = xn + yn - 2*dot; dot via bf16 hi/lo split on mma.sync (HMMA).
// Round 16: R15's ML-issued early B-prefetch, FIXED: a read barrier (armed
// by ML warps after each mainloop) gates the prefetch so no ML warp
// overwrites a buffer another ML warp is still reading (R15's race).
// EPI warps remain a pure drain (wait full -> exp -> STG).

#define NN 8192
#define DD 64
#define TILE 128
#define NSM 148
#define NCTA NSM                  // 148, 1 CTA/SM
#define NTHREADS 512
#define TOTTILES (64 * 64)        // 4096 tiles of 128x128

// smem: A 32K | B buf0 32K | B buf1 32K | stage0 64K | stage1 64K
#define AH_OFF 0
#define AL_OFF 16384
#define BH_OFF(buf) (32768 + (buf) * 32768)
#define BL_OFF(buf) (32768 + (buf) * 32768 + 16384)
#define STAGE_OFF(s) (98304 + (s) * 65536)
#define SMEM_DYN_BYTES 229376     // 224 KB

#define LOG2E      1.4426950408889634f
#define TWO_LOG2E  2.8853900817779268f

__device__ float g_xn[NN];   // ||x_i||^2 * log2(e)
__device__ float g_yn[NN];   // ||y_j||^2 * log2(e)
__device__ __nv_bfloat16 g_xh[NN * DD];
__device__ __nv_bfloat16 g_xl[NN * DD];
__device__ __nv_bfloat16 g_yh[NN * DD];
__device__ __nv_bfloat16 g_yl[NN * DD];

// ------------------------- helpers -----------------------------------------
__device__ __forceinline__ uint32_t smem_u32(const void* p) {
    uint32_t a;
    asm("{ .reg .u64 t; cvta.to.shared.u64 t, %1; cvt.u32.u64 %0, t; }"
        : "=r"(a) : "l"(p));
    return a;
}

__device__ __forceinline__ void cp_async16(uint32_t saddr, const void* gaddr) {
    asm volatile("cp.async.cg.shared.global [%0], [%1], 16;"
                 :: "r"(saddr), "l"(gaddr) : "memory");
}

__device__ __forceinline__ void mbar_init(uint32_t addr, uint32_t cnt) {
    asm volatile("mbarrier.init.shared.b64 [%0], %1;"
                 :: "r"(addr), "r"(cnt) : "memory");
}

__device__ __forceinline__ void cp_arrive_noinc(uint32_t addr) {
    asm volatile("cp.async.mbarrier.arrive.noinc.shared.b64 [%0];"
                 :: "r"(addr) : "memory");
}

__device__ __forceinline__ void mbar_arrive(uint32_t addr) {
    asm volatile("{ .reg .b64 tk; mbarrier.arrive.shared.b64 tk, [%0]; }"
                 :: "r"(addr) : "memory");
}

__device__ __forceinline__ void mbar_wait(uint32_t addr, uint32_t parity) {
    asm volatile(
        "{\n\t.reg .pred P1;\n\t"
        "WL_%=:\n\t"
        "mbarrier.try_wait.parity.acquire.cta.shared::cta.b64 P1, [%0], %1, 0x989680;\n\t"
        "@P1 bra.uni WD_%=;\n\t"
        "bra.uni WL_%=;\n\t"
        "WD_%=:\n\t}"
        :: "r"(addr), "r"(parity) : "memory");
}

__device__ __forceinline__ void ldsm4(uint32_t addr, uint32_t& r0, uint32_t& r1,
                                      uint32_t& r2, uint32_t& r3) {
    asm volatile("ldmatrix.sync.aligned.m8n8.x4.shared.b16 {%0,%1,%2,%3}, [%4];"
                 : "=r"(r0), "=r"(r1), "=r"(r2), "=r"(r3) : "r"(addr));
}

__device__ __forceinline__ void mma16816(float& c0, float& c1, float& c2, float& c3,
                                         uint32_t a0, uint32_t a1, uint32_t a2,
                                         uint32_t a3, uint32_t b0, uint32_t b1) {
    asm volatile(
        "mma.sync.aligned.m16n8k16.row.col.f32.bf16.bf16.f32 "
        "{%0,%1,%2,%3}, {%4,%5,%6,%7}, {%8,%9}, {%0,%1,%2,%3};"
        : "+f"(c0), "+f"(c1), "+f"(c2), "+f"(c3)
        : "r"(a0), "r"(a1), "r"(a2), "r"(a3), "r"(b0), "r"(b1));
}

__device__ __forceinline__ float ex2f(float v) {
    float r;
    asm("ex2.approx.ftz.f32 %0, %1;" : "=f"(r) : "f"(v));
    return r;
}

__device__ __forceinline__ uint32_t swz(uint32_t base, int row, int chunk) {
    return base + row * 128 + (((unsigned)chunk ^ ((unsigned)row & 7u)) << 4);
}

// acc stage: float2 units, 128 rows x 64 float2-cols (512B/row), col index
// XOR-swizzled with (row&7)<<2; XOR bits >=2 keep 16B adjacency -> LDS.128.
__device__ __forceinline__ uint32_t stage_addr(uint32_t stage_base, int row, int cp) {
    return stage_base + row * 512 +
           (((unsigned)cp ^ (((unsigned)row & 7u) << 2)) << 3);
}

__device__ __forceinline__ void sts64(uint32_t addr, float a, float b) {
    asm volatile("st.shared.v2.f32 [%0], {%1, %2};"
                 :: "r"(addr), "f"(a), "f"(b) : "memory");
}

__device__ __forceinline__ void lds128(uint32_t addr, float& a, float& b,
                                       float& c, float& d) {
    asm volatile("ld.shared.v4.f32 {%0, %1, %2, %3}, [%4];"
                 : "=f"(a), "=f"(b), "=f"(c), "=f"(d) : "r"(addr));
}

__device__ __forceinline__ void split2(float v0, float v1,
                                       uint32_t& hp, uint32_t& lp) {
    __nv_bfloat16 h0 = __float2bfloat16(v0);
    __nv_bfloat16 h1 = __float2bfloat16(v1);
    __nv_bfloat16 l0 = __float2bfloat16(v0 - __bfloat162float(h0));
    __nv_bfloat16 l1 = __float2bfloat16(v1 - __bfloat162float(h1));
    __nv_bfloat162 hh(h0, h1), ll(l0, l1);
    hp = *reinterpret_cast<uint32_t*>(&hh);
    lp = *reinterpret_cast<uint32_t*>(&ll);
}

// ---------------------------------------------------------------------------
__global__ void presplit_kernel(const float* __restrict__ x,
                                const float* __restrict__ y) {
    int tid = blockIdx.x * blockDim.x + threadIdx.x;
    int row = tid >> 4;
    int q = tid & 15;

    float4 vx = __ldg(reinterpret_cast<const float4*>(x + (size_t)row * DD) + q);
    float4 vy = __ldg(reinterpret_cast<const float4*>(y + (size_t)row * DD) + q);

    uint32_t h0, l0, h1, l1;
    split2(vx.x, vx.y, h0, l0);
    split2(vx.z, vx.w, h1, l1);
    *reinterpret_cast<uint2*>(&g_xh[(size_t)row * DD + q * 4]) = make_uint2(h0, h1);
    *reinterpret_cast<uint2*>(&g_xl[(size_t)row * DD + q * 4]) = make_uint2(l0, l1);
    split2(vy.x, vy.y, h0, l0);
    split2(vy.z, vy.w, h1, l1);
    *reinterpret_cast<uint2*>(&g_yh[(size_t)row * DD + q * 4]) = make_uint2(h0, h1);
    *reinterpret_cast<uint2*>(&g_yl[(size_t)row * DD + q * 4]) = make_uint2(l0, l1);

    float sx = vx.x * vx.x + vx.y * vx.y + vx.z * vx.z + vx.w * vx.w;
    float sy = vy.x * vy.x + vy.y * vy.y + vy.z * vy.z + vy.w * vy.w;
#pragma unroll
    for (int o = 8; o >= 1; o >>= 1) {
        sx += __shfl_xor_sync(0xffffffffu, sx, o, 16);
        sy += __shfl_xor_sync(0xffffffffu, sy, o, 16);
    }
    if (q == 0) {
        g_xn[row] = sx * LOG2E;
        g_yn[row] = sy * LOG2E;
    }
}

// ---------------------------------------------------------------------------
// tile fills: executed by the 256 ML threads (tl in 0..255)
__device__ __forceinline__ void load_A(uint32_t sbase, int tl, int row0) {
    const __nv_bfloat16* sh = g_xh + (size_t)row0 * DD;
    const __nv_bfloat16* sl = g_xl + (size_t)row0 * DD;
#pragma unroll
    for (int it = 0; it < 4; it++) {
        int idx = tl + 256 * it;   // 0..1023
        int r = idx >> 3;          // row 0..127
        int q = idx & 7;
        cp_async16(swz(sbase + AH_OFF, r, q), sh + (size_t)r * DD + q * 8);
        cp_async16(swz(sbase + AL_OFF, r, q), sl + (size_t)r * DD + q * 8);
    }
}

__device__ __forceinline__ void load_B(uint32_t sbase, int buf, int tl, int col0) {
    const __nv_bfloat16* sh = g_yh + (size_t)col0 * DD;
    const __nv_bfloat16* sl = g_yl + (size_t)col0 * DD;
    const uint32_t bh = sbase + BH_OFF(buf);
    const uint32_t bl = sbase + BL_OFF(buf);
#pragma unroll
    for (int it = 0; it < 4; it++) {
        int idx = tl + 256 * it;
        int r = idx >> 3;
        int q = idx & 7;
        cp_async16(swz(bh, r, q), sh + (size_t)r * DD + q * 8);
        cp_async16(swz(bl, r, q), sl + (size_t)r * DD + q * 8);
    }
}

// ---------------------------------------------------------------------------
// Persistent kernel: 512 threads. Warps 0-7 = ML (mma+fills), 8-15 = EPI.
// ---------------------------------------------------------------------------
__global__ __launch_bounds__(NTHREADS, 1)
void rbf_mma_kernel(float* __restrict__ out) {
    extern __shared__ __align__(128) char smem_raw[];
    const uint32_t sbase = smem_u32(smem_raw);

    // 0:fill0 1:fill1 2:read0 3:read1 4:full0 5:full1 6:free0 7:free1
    __shared__ __align__(8) uint64_t s_mbar[8];

    const int t    = threadIdx.x;
    const int wid  = t >> 5;
    const int lane = t & 31;
    const int b    = blockIdx.x;
    const bool is_ml = (t < 256);

    const uint32_t fill_a0 = smem_u32(&s_mbar[0]);
    const uint32_t fill_a1 = smem_u32(&s_mbar[1]);
    const uint32_t read_a0 = smem_u32(&s_mbar[2]);
    const uint32_t read_a1 = smem_u32(&s_mbar[3]);
    const uint32_t full_a0 = smem_u32(&s_mbar[4]);
    const uint32_t full_a1 = smem_u32(&s_mbar[5]);
    const uint32_t free_a0 = smem_u32(&s_mbar[6]);
    const uint32_t free_a1 = smem_u32(&s_mbar[7]);

    if (t == 0) {
#pragma unroll
        for (int i = 0; i < 8; i++) mbar_init(smem_u32(&s_mbar[i]), 256);
    }
    __syncthreads();

    // CTA tile run (contiguous, row-major over 64x64 tiles of 128x128)
    const int base  = TOTTILES / NCTA;
    const int rem   = TOTTILES % NCTA;
    const int cnt   = base + (b < rem);
    const int start = (b < rem) ? (base + 1) * b : rem * (base + 1) + base * (b - rem);

    if (is_ml) {
        // ====== ML warps: gated B self-prefetch + ldsm + mma + STS =========
        const int tl = t;                  // 0..255
        const int m_base = (wid >> 2) * 64;
        const int n_base = (wid & 3) * 32;
        const int a_row = m_base + (lane & 15);
        const int a_half = lane >> 4;
        const int b_row = n_base + ((lane >> 4) & 1) * 8 + (lane & 7);
        const int b_half = (lane >> 3) & 1;
        const int group = lane >> 2;
        const int tig   = lane & 3;

        // prologue: first tile's A + B into buf0
        load_A(sbase, tl, (start >> 6) * TILE);
        load_B(sbase, 0, tl, (start & 63) * TILE);
        cp_arrive_noinc(fill_a0);

        for (int u = 0; u < cnt; u++) {
            const int id   = start + u;
            const int ti   = id >> 6;
            const int buf  = u & 1;
            const uint32_t fill_cur = buf ? fill_a1 : fill_a0;
            const uint32_t fill_nxt = buf ? fill_a0 : fill_a1;
            const uint32_t read_cur = buf ? read_a1 : read_a0;
            const uint32_t read_oth = buf ? read_a0 : read_a1;  // buf^1
            const uint32_t full_cur = buf ? full_a1 : full_a0;
            const uint32_t free_cur = buf ? free_a1 : free_a0;

            // Gate writes into buf^1 (or A at strip entry): ALL ML warps must
            // have finished mainloop u-1 (which read buf^1). Cheap: waits
            // only for ML warp skew, not EPI.
            if (u > 0) mbar_wait(read_oth, ((u - 1) >> 1) & 1);

            // strip entry (rare): blocking reload of A + this tile's B
            if (u > 0 && (((id - 1) >> 6) != ti)) {
                load_A(sbase, tl, ti * TILE);
                load_B(sbase, buf, tl, (id & 63) * TILE);
                cp_arrive_noinc(fill_cur);
            }
            // EARLY prefetch of B(u+1) into buf^1 (now race-free)
            if (u + 1 < cnt && (((id + 1) >> 6) == ti)) {
                load_B(sbase, buf ^ 1, tl, ((id + 1) & 63) * TILE);
                cp_arrive_noinc(fill_nxt);
            }

            // wait for this tile's B (and A at strip entry)
            mbar_wait(fill_cur, (u >> 1) & 1);

            const uint32_t bhb = sbase + BH_OFF(buf);
            const uint32_t blb = sbase + BL_OFF(buf);

            float acc[4][4][4];
#pragma unroll
            for (int m = 0; m < 4; m++)
#pragma unroll
                for (int n = 0; n < 4; n++)
#pragma unroll
                    for (int e = 0; e < 4; e++) acc[m][n][e] = 0.f;

#pragma unroll
            for (int kc = 0; kc < 4; kc++) {
                const int a_chunk = kc * 2 + a_half;
                const int b_chunk = kc * 2 + b_half;

                uint32_t ah[4][4];
#pragma unroll
                for (int m = 0; m < 4; m++)
                    ldsm4(swz(sbase + AH_OFF, a_row + 16 * m, a_chunk),
                          ah[m][0], ah[m][1], ah[m][2], ah[m][3]);
                uint32_t bh[4][2];
#pragma unroll
                for (int p = 0; p < 2; p++)
                    ldsm4(swz(bhb, b_row + 16 * p, b_chunk),
                          bh[2 * p][0], bh[2 * p][1], bh[2 * p + 1][0], bh[2 * p + 1][1]);
#pragma unroll
                for (int m = 0; m < 4; m++)
#pragma unroll
                    for (int n = 0; n < 4; n++)
                        mma16816(acc[m][n][0], acc[m][n][1], acc[m][n][2], acc[m][n][3],
                                 ah[m][0], ah[m][1], ah[m][2], ah[m][3],
                                 bh[n][0], bh[n][1]);

                uint32_t bl[4][2];
#pragma unroll
                for (int p = 0; p < 2; p++)
                    ldsm4(swz(blb, b_row + 16 * p, b_chunk),
                          bl[2 * p][0], bl[2 * p][1], bl[2 * p + 1][0], bl[2 * p + 1][1]);
#pragma unroll
                for (int m = 0; m < 4; m++)
#pragma unroll
                    for (int n = 0; n < 4; n++)
                        mma16816(acc[m][n][0], acc[m][n][1], acc[m][n][2], acc[m][n][3],
                                 ah[m][0], ah[m][1], ah[m][2], ah[m][3],
                                 bl[n][0], bl[n][1]);

                uint32_t al[4][4];
#pragma unroll
                for (int m = 0; m < 4; m++)
                    ldsm4(swz(sbase + AL_OFF, a_row + 16 * m, a_chunk),
                          al[m][0], al[m][1], al[m][2], al[m][3]);
#pragma unroll
                for (int m = 0; m < 4; m++)
#pragma unroll
                    for (int n = 0; n < 4; n++)
                        mma16816(acc[m][n][0], acc[m][n][1], acc[m][n][2], acc[m][n][3],
                                 al[m][0], al[m][1], al[m][2], al[m][3],
                                 bh[n][0], bh[n][1]);
            }

            // signal: this ML thread finished reading buf (and A) for tile u
            mbar_arrive(read_cur);

            // stage buffer (u&1) must be drained of tile u-2 by EPI
            if (u >= 2) mbar_wait(free_cur, ((u >> 1) - 1) & 1);

            const uint32_t stg = sbase + STAGE_OFF(buf);
#pragma unroll
            for (int m = 0; m < 4; m++) {
                const int r0w = m_base + 16 * m + group;
#pragma unroll
                for (int n = 0; n < 4; n++) {
                    const int cp = (n_base >> 1) + 4 * n + tig;
                    sts64(stage_addr(stg, r0w, cp), acc[m][n][0], acc[m][n][1]);
                    sts64(stage_addr(stg, r0w + 8, cp), acc[m][n][2], acc[m][n][3]);
                }
            }
            mbar_arrive(full_cur);
        }
    } else {
        // ======== EPI warps: pure drain (exp + store; no loads/fills) ======
        const int we = wid - 8;            // 0..7
        const int row_base = we * 16;      // 16 rows per EPI warp

        for (int u = 0; u < cnt; u++) {
            const int id   = start + u;
            const int row0 = (id >> 6) * TILE;
            const int col0 = (id & 63) * TILE;
            const int buf  = u & 1;
            const uint32_t full_cur = buf ? full_a1 : full_a0;
            const uint32_t free_cur = buf ? free_a1 : free_a0;

            // y-norms: 4 consecutive cols per thread (L2-resident)
            const float4 yn4 = __ldg(reinterpret_cast<const float4*>(
                                         g_yn + col0 + 4 * lane));

            // wait for ML to publish this tile's accumulators
            mbar_wait(full_cur, (u >> 1) & 1);

            const uint32_t stg = sbase + STAGE_OFF(buf);
#pragma unroll 4
            for (int i = 0; i < 16; i++) {
                const int r = row_base + i;
                const float xn = __ldg(&g_xn[row0 + r]);
                float d0, d1, d2, d3;
                lds128(stage_addr(stg, r, 2 * lane), d0, d1, d2, d3);
                float4 e;
                e.x = ex2f(fmaf(TWO_LOG2E, d0, -(xn + yn4.x)));
                e.y = ex2f(fmaf(TWO_LOG2E, d1, -(xn + yn4.y)));
                e.z = ex2f(fmaf(TWO_LOG2E, d2, -(xn + yn4.z)));
                e.w = ex2f(fmaf(TWO_LOG2E, d3, -(xn + yn4.w)));
                __stcs(reinterpret_cast<float4*>(
                           out + (size_t)(row0 + r) * NN + col0 + 4 * lane), e);
            }
            mbar_arrive(free_cur);
        }
    }
}

// ---------------------------------------------------------------------------
extern "C" void kernel_launch(void* const* d_in, const int* in_sizes, int n_in,
                              void* d_out, int out_size) {
    const float* x = (const float*)d_in[0];
    const float* y = (const float*)d_in[1];
    float* out = (float*)d_out;
    (void)in_sizes; (void)n_in; (void)out_size;

    cudaFuncSetAttribute(rbf_mma_kernel,
                         cudaFuncAttributeMaxDynamicSharedMemorySize,
                         SMEM_DYN_BYTES);

    presplit_kernel<<<(NN * DD / 4) / 256, 256>>>(x, y);
    rbf_mma_kernel<<<NCTA, NTHREADS, SMEM_DYN_BYTES>>>(out);
}

// round 17
// speedup vs baseline: 1.1004x; 1.1004x over previous
#include <cuda_runtime.h>
#include <cuda_bf16.h>
#include <cstdint>

// RBF: out[i][j] = exp(-||x_i - y_j||^2), N=M=8192, D=64, fp32.
// dist2 = xn + yn - 2*dot; dot via bf16 hi/lo split on mma.sync (HMMA).
// Round 17: warp specialization (8 ML + 8 EPI warps) with TRIPLE-BUFFERED B
// and distance-2 prefetch: EPI at iter u prefetches B(u+2), giving ~2 tile
// times of fill slack. Buffer reuse is proven safe by the full(u-1)->iter u
// ordering, so NO read barriers exist. Stage is single 64KB (R13-proven
// sync) with the 128-bit EPI datapath.

#define NN 8192
#define DD 64
#define TILE 128
#define NSM 148
#define NCTA NSM                  // 148, 1 CTA/SM
#define NTHREADS 512
#define TOTTILES (64 * 64)        // 4096 tiles of 128x128

// smem: A 32K | B buf0/1/2 32K each | stage 64K  = 192 KB
#define AH_OFF 0
#define AL_OFF 16384
#define BH_OFF(buf) (32768 + (buf) * 32768)
#define BL_OFF(buf) (32768 + (buf) * 32768 + 16384)
#define STAGE_OFF 131072
#define SMEM_DYN_BYTES 196608     // 192 KB

#define LOG2E      1.4426950408889634f
#define TWO_LOG2E  2.8853900817779268f

__device__ float g_xn[NN];   // ||x_i||^2 * log2(e)
__device__ float g_yn[NN];   // ||y_j||^2 * log2(e)
__device__ __nv_bfloat16 g_xh[NN * DD];
__device__ __nv_bfloat16 g_xl[NN * DD];
__device__ __nv_bfloat16 g_yh[NN * DD];
__device__ __nv_bfloat16 g_yl[NN * DD];

// ------------------------- helpers -----------------------------------------
__device__ __forceinline__ uint32_t smem_u32(const void* p) {
    uint32_t a;
    asm("{ .reg .u64 t; cvta.to.shared.u64 t, %1; cvt.u32.u64 %0, t; }"
        : "=r"(a) : "l"(p));
    return a;
}

__device__ __forceinline__ void cp_async16(uint32_t saddr, const void* gaddr) {
    asm volatile("cp.async.cg.shared.global [%0], [%1], 16;"
                 :: "r"(saddr), "l"(gaddr) : "memory");
}

__device__ __forceinline__ void mbar_init(uint32_t addr, uint32_t cnt) {
    asm volatile("mbarrier.init.shared.b64 [%0], %1;"
                 :: "r"(addr), "r"(cnt) : "memory");
}

__device__ __forceinline__ void cp_arrive_noinc(uint32_t addr) {
    asm volatile("cp.async.mbarrier.arrive.noinc.shared.b64 [%0];"
                 :: "r"(addr) : "memory");
}

__device__ __forceinline__ void mbar_arrive(uint32_t addr) {
    asm volatile("{ .reg .b64 tk; mbarrier.arrive.shared.b64 tk, [%0]; }"
                 :: "r"(addr) : "memory");
}

__device__ __forceinline__ void mbar_wait(uint32_t addr, uint32_t parity) {
    asm volatile(
        "{\n\t.reg .pred P1;\n\t"
        "WL_%=:\n\t"
        "mbarrier.try_wait.parity.acquire.cta.shared::cta.b64 P1, [%0], %1, 0x989680;\n\t"
        "@P1 bra.uni WD_%=;\n\t"
        "bra.uni WL_%=;\n\t"
        "WD_%=:\n\t}"
        :: "r"(addr), "r"(parity) : "memory");
}

__device__ __forceinline__ void ldsm4(uint32_t addr, uint32_t& r0, uint32_t& r1,
                                      uint32_t& r2, uint32_t& r3) {
    asm volatile("ldmatrix.sync.aligned.m8n8.x4.shared.b16 {%0,%1,%2,%3}, [%4];"
                 : "=r"(r0), "=r"(r1), "=r"(r2), "=r"(r3) : "r"(addr));
}

__device__ __forceinline__ void mma16816(float& c0, float& c1, float& c2, float& c3,
                                         uint32_t a0, uint32_t a1, uint32_t a2,
                                         uint32_t a3, uint32_t b0, uint32_t b1) {
    asm volatile(
        "mma.sync.aligned.m16n8k16.row.col.f32.bf16.bf16.f32 "
        "{%0,%1,%2,%3}, {%4,%5,%6,%7}, {%8,%9}, {%0,%1,%2,%3};"
        : "+f"(c0), "+f"(c1), "+f"(c2), "+f"(c3)
        : "r"(a0), "r"(a1), "r"(a2), "r"(a3), "r"(b0), "r"(b1));
}

__device__ __forceinline__ float ex2f(float v) {
    float r;
    asm("ex2.approx.ftz.f32 %0, %1;" : "=f"(r) : "f"(v));
    return r;
}

__device__ __forceinline__ uint32_t swz(uint32_t base, int row, int chunk) {
    return base + row * 128 + (((unsigned)chunk ^ ((unsigned)row & 7u)) << 4);
}

// acc stage: float2 units, 128 rows x 64 float2-cols (512B/row), col index
// XOR-swizzled with (row&7)<<2; XOR bits >=2 keep 16B adjacency -> LDS.128.
__device__ __forceinline__ uint32_t stage_addr(uint32_t stage_base, int row, int cp) {
    return stage_base + row * 512 +
           (((unsigned)cp ^ (((unsigned)row & 7u) << 2)) << 3);
}

__device__ __forceinline__ void sts64(uint32_t addr, float a, float b) {
    asm volatile("st.shared.v2.f32 [%0], {%1, %2};"
                 :: "r"(addr), "f"(a), "f"(b) : "memory");
}

__device__ __forceinline__ void lds128(uint32_t addr, float& a, float& b,
                                       float& c, float& d) {
    asm volatile("ld.shared.v4.f32 {%0, %1, %2, %3}, [%4];"
                 : "=f"(a), "=f"(b), "=f"(c), "=f"(d) : "r"(addr));
}

__device__ __forceinline__ void split2(float v0, float v1,
                                       uint32_t& hp, uint32_t& lp) {
    __nv_bfloat16 h0 = __float2bfloat16(v0);
    __nv_bfloat16 h1 = __float2bfloat16(v1);
    __nv_bfloat16 l0 = __float2bfloat16(v0 - __bfloat162float(h0));
    __nv_bfloat16 l1 = __float2bfloat16(v1 - __bfloat162float(h1));
    __nv_bfloat162 hh(h0, h1), ll(l0, l1);
    hp = *reinterpret_cast<uint32_t*>(&hh);
    lp = *reinterpret_cast<uint32_t*>(&ll);
}

// ---------------------------------------------------------------------------
__global__ void presplit_kernel(const float* __restrict__ x,
                                const float* __restrict__ y) {
    int tid = blockIdx.x * blockDim.x + threadIdx.x;
    int row = tid >> 4;
    int q = tid & 15;

    float4 vx = __ldg(reinterpret_cast<const float4*>(x + (size_t)row * DD) + q);
    float4 vy = __ldg(reinterpret_cast<const float4*>(y + (size_t)row * DD) + q);

    uint32_t h0, l0, h1, l1;
    split2(vx.x, vx.y, h0, l0);
    split2(vx.z, vx.w, h1, l1);
    *reinterpret_cast<uint2*>(&g_xh[(size_t)row * DD + q * 4]) = make_uint2(h0, h1);
    *reinterpret_cast<uint2*>(&g_xl[(size_t)row * DD + q * 4]) = make_uint2(l0, l1);
    split2(vy.x, vy.y, h0, l0);
    split2(vy.z, vy.w, h1, l1);
    *reinterpret_cast<uint2*>(&g_yh[(size_t)row * DD + q * 4]) = make_uint2(h0, h1);
    *reinterpret_cast<uint2*>(&g_yl[(size_t)row * DD + q * 4]) = make_uint2(l0, l1);

    float sx = vx.x * vx.x + vx.y * vx.y + vx.z * vx.z + vx.w * vx.w;
    float sy = vy.x * vy.x + vy.y * vy.y + vy.z * vy.z + vy.w * vy.w;
#pragma unroll
    for (int o = 8; o >= 1; o >>= 1) {
        sx += __shfl_xor_sync(0xffffffffu, sx, o, 16);
        sy += __shfl_xor_sync(0xffffffffu, sy, o, 16);
    }
    if (q == 0) {
        g_xn[row] = sx * LOG2E;
        g_yn[row] = sy * LOG2E;
    }
}

// ---------------------------------------------------------------------------
// tile fills: executed by the 256 EPI threads (tl in 0..255)
__device__ __forceinline__ void load_A(uint32_t sbase, int tl, int row0) {
    const __nv_bfloat16* sh = g_xh + (size_t)row0 * DD;
    const __nv_bfloat16* sl = g_xl + (size_t)row0 * DD;
#pragma unroll
    for (int it = 0; it < 4; it++) {
        int idx = tl + 256 * it;   // 0..1023
        int r = idx >> 3;          // row 0..127
        int q = idx & 7;
        cp_async16(swz(sbase + AH_OFF, r, q), sh + (size_t)r * DD + q * 8);
        cp_async16(swz(sbase + AL_OFF, r, q), sl + (size_t)r * DD + q * 8);
    }
}

__device__ __forceinline__ void load_B(uint32_t sbase, int buf, int tl, int col0) {
    const __nv_bfloat16* sh = g_yh + (size_t)col0 * DD;
    const __nv_bfloat16* sl = g_yl + (size_t)col0 * DD;
    const uint32_t bh = sbase + BH_OFF(buf);
    const uint32_t bl = sbase + BL_OFF(buf);
#pragma unroll
    for (int it = 0; it < 4; it++) {
        int idx = tl + 256 * it;
        int r = idx >> 3;
        int q = idx & 7;
        cp_async16(swz(bh, r, q), sh + (size_t)r * DD + q * 8);
        cp_async16(swz(bl, r, q), sl + (size_t)r * DD + q * 8);
    }
}

// ---------------------------------------------------------------------------
// Persistent kernel: 512 threads. Warps 0-7 = ML (mma), warps 8-15 = EPI.
// ---------------------------------------------------------------------------
__global__ __launch_bounds__(NTHREADS, 1)
void rbf_mma_kernel(float* __restrict__ out) {
    extern __shared__ __align__(128) char smem_raw[];
    const uint32_t sbase = smem_u32(smem_raw);

    // 0:fill0 1:fill1 2:fill2 3:full 4:free
    __shared__ __align__(8) uint64_t s_mbar[5];

    const int t    = threadIdx.x;
    const int wid  = t >> 5;
    const int lane = t & 31;
    const int b    = blockIdx.x;
    const bool is_ml = (t < 256);

    const uint32_t fill_a[3] = {smem_u32(&s_mbar[0]), smem_u32(&s_mbar[1]),
                                smem_u32(&s_mbar[2])};
    const uint32_t full_a = smem_u32(&s_mbar[3]);
    const uint32_t free_a = smem_u32(&s_mbar[4]);

    if (t == 0) {
#pragma unroll
        for (int i = 0; i < 5; i++) mbar_init(smem_u32(&s_mbar[i]), 256);
    }
    __syncthreads();

    // CTA tile run (contiguous, row-major over 64x64 tiles of 128x128)
    const int base  = TOTTILES / NCTA;
    const int rem   = TOTTILES % NCTA;
    const int cnt   = base + (b < rem);
    const int start = (b < rem) ? (base + 1) * b : rem * (base + 1) + base * (b - rem);

    if (is_ml) {
        // ========== ML warps: wait fill -> mainloop -> STS stage ==========
        const int m_base = (wid >> 2) * 64;
        const int n_base = (wid & 3) * 32;
        const int a_row = m_base + (lane & 15);
        const int a_half = lane >> 4;
        const int b_row = n_base + ((lane >> 4) & 1) * 8 + (lane & 7);
        const int b_half = (lane >> 3) & 1;
        const int group = lane >> 2;
        const int tig   = lane & 3;

        int bu = 0;   // buffer index u % 3
        int fp = 0;   // fill parity (u / 3) & 1

        for (int u = 0; u < cnt; u++) {
            // wait for this tile's B (and A at strip entry) in buf bu
            mbar_wait(fill_a[bu], fp);

            const uint32_t bhb = sbase + BH_OFF(bu);
            const uint32_t blb = sbase + BL_OFF(bu);

            float acc[4][4][4];
#pragma unroll
            for (int m = 0; m < 4; m++)
#pragma unroll
                for (int n = 0; n < 4; n++)
#pragma unroll
                    for (int e = 0; e < 4; e++) acc[m][n][e] = 0.f;

#pragma unroll
            for (int kc = 0; kc < 4; kc++) {
                const int a_chunk = kc * 2 + a_half;
                const int b_chunk = kc * 2 + b_half;

                uint32_t ah[4][4];
#pragma unroll
                for (int m = 0; m < 4; m++)
                    ldsm4(swz(sbase + AH_OFF, a_row + 16 * m, a_chunk),
                          ah[m][0], ah[m][1], ah[m][2], ah[m][3]);
                uint32_t bh[4][2];
#pragma unroll
                for (int p = 0; p < 2; p++)
                    ldsm4(swz(bhb, b_row + 16 * p, b_chunk),
                          bh[2 * p][0], bh[2 * p][1], bh[2 * p + 1][0], bh[2 * p + 1][1]);
#pragma unroll
                for (int m = 0; m < 4; m++)
#pragma unroll
                    for (int n = 0; n < 4; n++)
                        mma16816(acc[m][n][0], acc[m][n][1], acc[m][n][2], acc[m][n][3],
                                 ah[m][0], ah[m][1], ah[m][2], ah[m][3],
                                 bh[n][0], bh[n][1]);

                uint32_t bl[4][2];
#pragma unroll
                for (int p = 0; p < 2; p++)
                    ldsm4(swz(blb, b_row + 16 * p, b_chunk),
                          bl[2 * p][0], bl[2 * p][1], bl[2 * p + 1][0], bl[2 * p + 1][1]);
#pragma unroll
                for (int m = 0; m < 4; m++)
#pragma unroll
                    for (int n = 0; n < 4; n++)
                        mma16816(acc[m][n][0], acc[m][n][1], acc[m][n][2], acc[m][n][3],
                                 ah[m][0], ah[m][1], ah[m][2], ah[m][3],
                                 bl[n][0], bl[n][1]);

                uint32_t al[4][4];
#pragma unroll
                for (int m = 0; m < 4; m++)
                    ldsm4(swz(sbase + AL_OFF, a_row + 16 * m, a_chunk),
                          al[m][0], al[m][1], al[m][2], al[m][3]);
#pragma unroll
                for (int m = 0; m < 4; m++)
#pragma unroll
                    for (int n = 0; n < 4; n++)
                        mma16816(acc[m][n][0], acc[m][n][1], acc[m][n][2], acc[m][n][3],
                                 al[m][0], al[m][1], al[m][2], al[m][3],
                                 bh[n][0], bh[n][1]);
            }

            // stage must be drained of tile u-1 by EPI
            if (u > 0) mbar_wait(free_a, (u - 1) & 1);

#pragma unroll
            for (int m = 0; m < 4; m++) {
                const int r0w = m_base + 16 * m + group;
#pragma unroll
                for (int n = 0; n < 4; n++) {
                    const int cp = (n_base >> 1) + 4 * n + tig;
                    sts64(stage_addr(sbase + STAGE_OFF, r0w, cp),
                          acc[m][n][0], acc[m][n][1]);
                    sts64(stage_addr(sbase + STAGE_OFF, r0w + 8, cp),
                          acc[m][n][2], acc[m][n][3]);
                }
            }
            mbar_arrive(full_a);

            if (++bu == 3) { bu = 0; fp ^= 1; }
        }
    } else {
        // ====== EPI warps: distance-2 B prefetch + A loads + drain ========
        const int tl = t - 256;            // 0..255
        const int we = wid - 8;            // 0..7
        const int row_base = we * 16;      // 16 rows per EPI warp

        // prologue: A(strip0) + B(0)->buf0 armed; B(1)->buf1 (arm unless
        // tile 1 is a strip entry; then its arm happens at iter 0 step 4)
        load_A(sbase, tl, (start >> 6) * TILE);
        load_B(sbase, 0, tl, (start & 63) * TILE);
        cp_arrive_noinc(fill_a[0]);
        if (cnt > 1) {
            load_B(sbase, 1, tl, ((start + 1) & 63) * TILE);
            if (((start + 1) & 63) != 0) cp_arrive_noinc(fill_a[1]);
        }

        int bn = 2;   // buffer for tile u+2

        for (int u = 0; u < cnt; u++) {
            const int id   = start + u;
            const int row0 = (id >> 6) * TILE;
            const int col0 = (id & 63) * TILE;

            // 1. distance-2 prefetch: B(u+2) into buf bn. Safe: we are past
            // full(u-1), so ML's mainloop u-1 (last reader of bn) is done.
            if (u + 2 < cnt) {
                load_B(sbase, bn, tl, ((id + 2) & 63) * TILE);
                if (((id + 2) & 63) != 0) cp_arrive_noinc(fill_a[bn]);
                // strip-entry tile: arm deferred until its A is loaded
            }

            // 2. y-norms for this thread's 4 output columns
            const float4 yn4 = __ldg(reinterpret_cast<const float4*>(
                                         g_yn + col0 + 4 * lane));

            // 3. wait for ML to publish this tile's accumulators
            mbar_wait(full_a, u & 1);

            // 4. strip entry at tile u+1: mainloop u is done (full(u) just
            // fired), so A can be reloaded now; arm covers pending B(u+1).
            if (u + 1 < cnt && ((id + 1) & 63) == 0) {
                load_A(sbase, tl, ((id + 1) >> 6) * TILE);
                int b1 = (u + 1) % 3;
                cp_arrive_noinc(fill_a[b1]);
            }

            // 5. drain stage -> exp -> coalesced STG.128
#pragma unroll 4
            for (int i = 0; i < 16; i++) {
                const int r = row_base + i;
                const float xn = __ldg(&g_xn[row0 + r]);
                float d0, d1, d2, d3;
                lds128(stage_addr(sbase + STAGE_OFF, r, 2 * lane), d0, d1, d2, d3);
                float4 e;
                e.x = ex2f(fmaf(TWO_LOG2E, d0, -(xn + yn4.x)));
                e.y = ex2f(fmaf(TWO_LOG2E, d1, -(xn + yn4.y)));
                e.z = ex2f(fmaf(TWO_LOG2E, d2, -(xn + yn4.z)));
                e.w = ex2f(fmaf(TWO_LOG2E, d3, -(xn + yn4.w)));
                __stcs(reinterpret_cast<float4*>(
                           out + (size_t)(row0 + r) * NN + col0 + 4 * lane), e);
            }
            mbar_arrive(free_a);

            if (++bn == 3) bn = 0;
        }
    }
}

// ---------------------------------------------------------------------------
extern "C" void kernel_launch(void* const* d_in, const int* in_sizes, int n_in,
                              void* d_out, int out_size) {
    const float* x = (const float*)d_in[0];
    const float* y = (const float*)d_in[1];
    float* out = (float*)d_out;
    (void)in_sizes; (void)n_in; (void)out_size;

    cudaFuncSetAttribute(rbf_mma_kernel,
                         cudaFuncAttributeMaxDynamicSharedMemorySize,
                         SMEM_DYN_BYTES);

    presplit_kernel<<<(NN * DD / 4) / 256, 256>>>(x, y);
    rbf_mma_kernel<<<NCTA, NTHREADS, SMEM_DYN_BYTES>>>(out);
}